// round 17
// baseline (speedup 1.0000x reference)
#include <cuda_runtime.h>
#include <cuda_fp16.h>
#include <cstdint>

// Problem constants
#define BB  8
#define NN_ 2048
#define DD  128
#define NH  8
#define NL  4
#define NCHUNK 16                    // gram split-K chunks (128 rows each)

// f16 tiles: row stride SPH uint32 (=136 halves, 128 used). SPH%32==4 ->
// ldmatrix 8-row reads cover all 32 banks exactly (conflict-free).
#define SPH 68
#define T64U  (64 * SPH)
#define T128U (128 * SPH)
#define SM_GRAM (T128U * 4)              // 34816 B
#define SM_QG   ((T64U + T128U) * 4)     // 52224 B
#define SM_UPD  (2 * T128U * 4)          // 69632 B

// Scratch
__device__ float g_Gp[NCHUNK * BB * DD * DD];  // gram partials (8.4MB, f32)
__device__ float g_G[BB * DD * DD];            // reduced Gram (f32)
__device__ float g_Mt[BB * DD * DD];           // Mt[n][k] = M[k][n]  (f32)

// ---------------------------------------------------------------------------
__device__ __forceinline__ uint32_t pack2(float lo, float hi) {
    __half2 h = __floats2half2_rn(lo, hi);     // lo -> low 16 bits
    return *reinterpret_cast<uint32_t*>(&h);
}

// f32 gmem row-major [NR x 128] -> f16 smem tile [NR][SPH] (k-contiguous rows).
template<int NR, int NT>
__device__ __forceinline__ void cvt_fill(uint32_t* S, const float* __restrict__ g, int tid) {
    const float4* s4 = (const float4*)g;
#pragma unroll
    for (int it = 0; it < NR * 32 / NT; it++) {
        int i4 = it * NT + tid;
        int r = i4 >> 5, c4 = i4 & 31;
        float4 v = s4[i4];
        uint2 o = make_uint2(pack2(v.x, v.y), pack2(v.z, v.w));
        *(uint2*)(S + r * SPH + c4 * 2) = o;
    }
}

// ---------------------------------------------------------------------------
#define LDM_X4(r0, r1, r2, r3, addr) \
    asm volatile("ldmatrix.sync.aligned.m8n8.x4.shared.b16 {%0,%1,%2,%3}, [%4];" \
        : "=r"(r0), "=r"(r1), "=r"(r2), "=r"(r3) : "r"(addr))
#define LDM_X4T(r0, r1, r2, r3, addr) \
    asm volatile("ldmatrix.sync.aligned.m8n8.x4.trans.shared.b16 {%0,%1,%2,%3}, [%4];" \
        : "=r"(r0), "=r"(r1), "=r"(r2), "=r"(r3) : "r"(addr))

template<int MI>
__device__ __forceinline__ void mma_frag_h(float (&acc)[MI][4][4],
                                           const uint32_t (&a)[MI][4],
                                           const uint32_t (&b)[4][2]) {
#pragma unroll
    for (int mi = 0; mi < MI; mi++)
#pragma unroll
        for (int ni = 0; ni < 4; ni++)
            asm("mma.sync.aligned.m16n8k16.row.col.f32.f16.f16.f32 "
                "{%0,%1,%2,%3}, {%4,%5,%6,%7}, {%8,%9}, {%0,%1,%2,%3};"
                : "+f"(acc[mi][ni][0]), "+f"(acc[mi][ni][1]),
                  "+f"(acc[mi][ni][2]), "+f"(acc[mi][ni][3])
                : "r"(a[mi][0]), "r"(a[mi][1]), "r"(a[mi][2]), "r"(a[mi][3]),
                  "r"(b[ni][0]), "r"(b[ni][1]));
}

// GEMM, A normal [m][k], B normal [n][k], K=128, ldmatrix fragments, dbuf.
template<int MI>
__device__ __forceinline__ void wgemm_nn(const uint32_t* A, const uint32_t* B,
                                         float (&acc)[MI][4][4], int wm, int wn, int lane) {
    uint32_t Ab = (uint32_t)__cvta_generic_to_shared(A);
    uint32_t Bb = (uint32_t)__cvta_generic_to_shared(B);
    const int l7 = lane & 7, s3 = (lane >> 3) & 1, s4 = (lane >> 4) & 1;
    uint32_t aA[MI];
#pragma unroll
    for (int mi = 0; mi < MI; mi++)
        aA[mi] = Ab + (uint32_t)(((wm + mi * 16 + l7 + s3 * 8) * SPH + s4 * 4) * 4);
    uint32_t aB0 = Bb + (uint32_t)(((wn + l7 + s4 * 8) * SPH + s3 * 4) * 4);
    uint32_t aB1 = aB0 + 16 * SPH * 4;

    uint32_t a0[MI][4], b0[4][2], a1[MI][4], b1[4][2];
    auto LF = [&](uint32_t (&a)[MI][4], uint32_t (&b)[4][2], int ks) {
        const uint32_t off = (uint32_t)ks * 32u;   // 8 uint32 of k per step
#pragma unroll
        for (int mi = 0; mi < MI; mi++)
            LDM_X4(a[mi][0], a[mi][1], a[mi][2], a[mi][3], aA[mi] + off);
        LDM_X4(b[0][0], b[0][1], b[1][0], b[1][1], aB0 + off);
        LDM_X4(b[2][0], b[2][1], b[3][0], b[3][1], aB1 + off);
    };
    LF(a0, b0, 0);
#pragma unroll
    for (int ks = 0; ks < 8; ks += 2) {
        if (ks + 1 < 8) LF(a1, b1, ks + 1);
        mma_frag_h<MI>(acc, a0, b0);
        if (ks + 2 < 8) LF(a0, b0, ks + 2);
        if (ks + 1 < 8) mma_frag_h<MI>(acc, a1, b1);
    }
}

// GEMM for Gram: operands logically transposed. S = normal tile [row][feat];
// computes acc[m][n] = sum_row S[row][m] * S[row][n] via ldmatrix.trans.
template<int MI>
__device__ __forceinline__ void wgemm_tt(const uint32_t* A, const uint32_t* B,
                                         float (&acc)[MI][4][4], int wm, int wn, int lane) {
    uint32_t Ab = (uint32_t)__cvta_generic_to_shared(A);
    uint32_t Bb = (uint32_t)__cvta_generic_to_shared(B);
    const int l7 = lane & 7, s3 = (lane >> 3) & 1, s4 = (lane >> 4) & 1;
    uint32_t aA[MI];
#pragma unroll
    for (int mi = 0; mi < MI; mi++)
        aA[mi] = Ab + (uint32_t)(((l7 + s4 * 8) * SPH) * 4 + (wm + mi * 16 + s3 * 8) * 2);
    uint32_t aB0 = Bb + (uint32_t)(((l7 + s3 * 8) * SPH) * 4 + (wn + s4 * 8) * 2);
    uint32_t aB1 = aB0 + 16 * 2;

    uint32_t a0[MI][4], b0[4][2], a1[MI][4], b1[4][2];
    auto LF = [&](uint32_t (&a)[MI][4], uint32_t (&b)[4][2], int ks) {
        const uint32_t off = (uint32_t)ks * (16u * SPH * 4u);   // 16 stored rows per step
#pragma unroll
        for (int mi = 0; mi < MI; mi++)
            LDM_X4T(a[mi][0], a[mi][1], a[mi][2], a[mi][3], aA[mi] + off);
        LDM_X4T(b[0][0], b[0][1], b[1][0], b[1][1], aB0 + off);
        LDM_X4T(b[2][0], b[2][1], b[3][0], b[3][1], aB1 + off);
    };
    LF(a0, b0, 0);
#pragma unroll
    for (int ks = 0; ks < 8; ks += 2) {
        if (ks + 1 < 8) LF(a1, b1, ks + 1);
        mma_frag_h<MI>(acc, a0, b0);
        if (ks + 2 < 8) LF(a0, b0, ks + 2);
        if (ks + 1 < 8) mma_frag_h<MI>(acc, a1, b1);
    }
}

#define ZERO_ACC(acc, MI) do { \
    _Pragma("unroll") for (int _i = 0; _i < (MI); _i++) \
    _Pragma("unroll") for (int _j = 0; _j < 4; _j++) \
    _Pragma("unroll") for (int _k = 0; _k < 4; _k++) acc[_i][_j][_k] = 0.0f; } while (0)

template<int MI>
__device__ __forceinline__ void store_part(float* P, float (&acc)[MI][4][4],
                                           int wm, int wn, int lane) {
    const int g = lane >> 2, t = lane & 3;
#pragma unroll
    for (int mi = 0; mi < MI; mi++)
#pragma unroll
        for (int ni = 0; ni < 4; ni++) {
            const int r = wm + mi * 16 + g, c = wn + ni * 8 + 2 * t;
            *(float2*)&P[(size_t)r * DD + c] =
                make_float2(acc[mi][ni][0], acc[mi][ni][1]);
            *(float2*)&P[(size_t)(r + 8) * DD + c] =
                make_float2(acc[mi][ni][2], acc[mi][ni][3]);
        }
}

// ---------------------------------------------------------------------------
// gram_part: Gp[s][b] = Zc^T @ Zc (128-row chunk). grid (16, B), 512 thr.
// Normal-layout tile + ldmatrix.trans for both operands.
__global__ __launch_bounds__(512, 1) void gram_part(const float* __restrict__ Z) {
    extern __shared__ uint32_t smem[];
    const int b = blockIdx.y, s = blockIdx.x;
    const int tid = threadIdx.x, wid = tid >> 5, lane = tid & 31;

    cvt_fill<128, 512>(smem, Z + ((size_t)b * NN_ + (size_t)s * 128) * DD, tid);
    __syncthreads();

    float acc[2][4][4];
    ZERO_ACC(acc, 2);
    const int wm = (wid >> 2) * 32, wn = (wid & 3) * 32;
    wgemm_tt<2>(smem, smem, acc, wm, wn, lane);

    store_part<2>(g_Gp + ((size_t)s * BB + b) * DD * DD, acc, wm, wn, lane);
}

// ---------------------------------------------------------------------------
// greduce: G[b] = sum_s Gp[s][b]; zeroes Mt. grid 128, 256 thr (float4).
__global__ __launch_bounds__(256) void greduce() {
    const int idx = blockIdx.x * 256 + threadIdx.x;
    const int b = idx >> 12, i4 = idx & 4095;
    const float4* P = (const float4*)g_Gp;
    float4 s = make_float4(0.f, 0.f, 0.f, 0.f);
#pragma unroll
    for (int c = 0; c < NCHUNK; c++) {
        float4 v = P[((size_t)c * BB + b) * 4096 + i4];
        s.x += v.x; s.y += v.y; s.z += v.z; s.w += v.w;
    }
    ((float4*)g_G)[idx] = s;
    ((float4*)g_Mt)[idx] = make_float4(0.f, 0.f, 0.f, 0.f);
}

// ---------------------------------------------------------------------------
// qgtv: T = Q_j[64 rows] @ G_b; Mt[b] += (T @ V_j^T)^T / (N*NH).
// grid (2, B*NH), 256 thr. B operands normal: G symmetric; V natural [n][k].
__global__ __launch_bounds__(256, 2) void qgtv(const float* __restrict__ Qm,
                                               const float* __restrict__ Vm) {
    extern __shared__ uint32_t smem[];
    uint32_t* bufA = smem;           // 64 x SPH  (Q, then T)
    uint32_t* bufB = smem + T64U;    // 128 x SPH (G, then V)
    const int half = blockIdx.x, bj = blockIdx.y, b = bj >> 3, j = bj & 7;
    const int tid = threadIdx.x, wid = tid >> 5, lane = tid & 31;
    const int g = lane >> 2, t = lane & 3;
    const int wm = (wid >> 2) * 32, wn = (wid & 3) * 32;

    cvt_fill<64, 256>(bufA, Qm + (size_t)j * DD * DD + (size_t)half * 64 * DD, tid);
    cvt_fill<128, 256>(bufB, g_G + (size_t)b * DD * DD, tid);
    __syncthreads();

    float acc[2][4][4];
    ZERO_ACC(acc, 2);
    wgemm_nn<2>(bufA, bufB, acc, wm, wn, lane);      // T = Q @ G
    __syncthreads();

    {   // T (f16 pairs) into bufA; V into bufB
#pragma unroll
        for (int mi = 0; mi < 2; mi++)
#pragma unroll
            for (int ni = 0; ni < 4; ni++) {
                const int r = wm + mi * 16 + g, c = wn + ni * 8 + 2 * t;
                bufA[r * SPH + (c >> 1)]       = pack2(acc[mi][ni][0], acc[mi][ni][1]);
                bufA[(r + 8) * SPH + (c >> 1)] = pack2(acc[mi][ni][2], acc[mi][ni][3]);
            }
        cvt_fill<128, 256>(bufB, Vm + (size_t)j * DD * DD, tid);
    }
    __syncthreads();

    ZERO_ACC(acc, 2);
    wgemm_nn<2>(bufA, bufB, acc, wm, wn, lane);      // M = T @ V^T

    float* Mb = g_Mt + (size_t)b * DD * DD;          // Mt[n][k]
    const float S = 1.0f / ((float)NN_ * (float)NH);
#pragma unroll
    for (int mi = 0; mi < 2; mi++)
#pragma unroll
        for (int ni = 0; ni < 4; ni++) {
            const int r = half * 64 + wm + mi * 16 + g, c = wn + ni * 8 + 2 * t;
            atomicAdd(&Mb[(size_t)c * DD + r],           acc[mi][ni][0] * S);
            atomicAdd(&Mb[(size_t)(c + 1) * DD + r],     acc[mi][ni][1] * S);
            atomicAdd(&Mb[(size_t)c * DD + r + 8],       acc[mi][ni][2] * S);
            atomicAdd(&Mb[(size_t)(c + 1) * DD + r + 8], acc[mi][ni][3] * S);
        }
}

// ---------------------------------------------------------------------------
// update: Zout = Zin + Zin @ M[b] (128-row chunks, in-place safe), then fused
// next-layer Gram partial via ldmatrix.trans on the refilled bufA (Zout f16,
// normal layout -> no conflicted transposed stores). grid (16, B), 512 thr.
__global__ __launch_bounds__(512, 1) void update(const float* __restrict__ Zin,
                                                 float* __restrict__ Zout, int do_gram) {
    extern __shared__ uint32_t smem[];
    uint32_t* bufA = smem;             // Zin f16 -> (epilogue) Zout f16
    uint32_t* bufB = smem + T128U;     // Mt f16 (Bs[n][k] = M[k][n])
    const int b = blockIdx.y, s = blockIdx.x;
    const int tid = threadIdx.x, wid = tid >> 5, lane = tid & 31;
    const int g = lane >> 2, t = lane & 3;
    const size_t zoff = ((size_t)b * NN_ + (size_t)s * 128) * DD;

    cvt_fill<128, 512>(bufA, Zin + zoff, tid);
    cvt_fill<128, 512>(bufB, g_Mt + (size_t)b * DD * DD, tid);
    __syncthreads();

    float acc[2][4][4];
    ZERO_ACC(acc, 2);
    const int wm = (wid >> 2) * 32, wn = (wid & 3) * 32;
    wgemm_nn<2>(bufA, bufB, acc, wm, wn, lane);
    __syncthreads();   // all warps done reading bufA before overwrite

    // Epilogue: out = Zin(f32) + acc; stash f16 Zout (normal layout) into bufA.
#pragma unroll
    for (int mi = 0; mi < 2; mi++)
#pragma unroll
        for (int ni = 0; ni < 4; ni++) {
            const int r = wm + mi * 16 + g, c = wn + ni * 8 + 2 * t;
            const float2 z0 = *(const float2*)&Zin[zoff + (size_t)r * DD + c];
            const float2 z1 = *(const float2*)&Zin[zoff + (size_t)(r + 8) * DD + c];
            float2 o0 = make_float2(z0.x + acc[mi][ni][0], z0.y + acc[mi][ni][1]);
            float2 o1 = make_float2(z1.x + acc[mi][ni][2], z1.y + acc[mi][ni][3]);
            *(float2*)&Zout[zoff + (size_t)r * DD + c]       = o0;
            *(float2*)&Zout[zoff + (size_t)(r + 8) * DD + c] = o1;
            if (do_gram) {
                bufA[r * SPH + (c >> 1)]       = pack2(o0.x, o0.y);
                bufA[(r + 8) * SPH + (c >> 1)] = pack2(o1.x, o1.y);
            }
        }

    if (!do_gram) return;
    __syncthreads();

    // Fused gram partial: Gp[s][b] = Zout^T @ Zout (trans ldmatrix on bufA).
    float acc2[2][4][4];
    ZERO_ACC(acc2, 2);
    wgemm_tt<2>(bufA, bufA, acc2, wm, wn, lane);
    store_part<2>(g_Gp + ((size_t)s * BB + b) * DD * DD, acc2, wm, wn, lane);
}

// ---------------------------------------------------------------------------
extern "C" void kernel_launch(void* const* d_in, const int* in_sizes, int n_in,
                              void* d_out, int out_size) {
    const float* Z  = (const float*)d_in[0];
    const float* Vm = (const float*)d_in[1];  // [NL, NH, 1, D, D]
    const float* Qm = (const float*)d_in[2];  // [NL, NH, 1, D, D]
    float* out = (float*)d_out;

    cudaFuncSetAttribute(gram_part, cudaFuncAttributeMaxDynamicSharedMemorySize, SM_GRAM);
    cudaFuncSetAttribute(qgtv,      cudaFuncAttributeMaxDynamicSharedMemorySize, SM_QG);
    cudaFuncSetAttribute(update,    cudaFuncAttributeMaxDynamicSharedMemorySize, SM_UPD);

    gram_part<<<dim3(NCHUNK, BB), 512, SM_GRAM>>>(Z);
    for (int l = 0; l < NL; l++) {
        const float* Zin = (l == 0) ? Z : out;
        greduce<<<128, 256>>>();
        qgtv<<<dim3(2, BB * NH), 256, SM_QG>>>(Qm + (size_t)l * NH * DD * DD,
                                               Vm + (size_t)l * NH * DD * DD);
        update<<<dim3(NCHUNK, BB), 512, SM_UPD>>>(Zin, out, l < NL - 1);
    }
}